// round 13
// baseline (speedup 1.0000x reference)
#include <cuda_runtime.h>
#include <cuda_bf16.h>
#include <math.h>

#define N_QUERIES 8192
#define N_WAY 5
#define DIM 256
#define WARPS_PER_BLOCK 4
#define GRID_BLOCKS (N_QUERIES / WARPS_PER_BLOCK)   // 2048

// Accumulators. Zero at module load; the last finishing block resets them
// after producing the output, so every graph replay starts from zero.
__device__ double       g_loss_sum = 0.0;
__device__ int          g_correct  = 0;
__device__ unsigned int g_ticket   = 0;

struct Vec8 { float f[8]; };

// 256-bit read-only load with L2 evict_last. The 48 MB input fits in ~126 MB
// L2 and the harness replays the graph back-to-back; keeping lines resident
// should turn DRAM traffic into L2 hits on replays after the first.
// 128-thread blocks keep occupancy at ~69% (11 blocks/SM at 44 regs) so the
// cache-policy effect is isolated from the occupancy confound of R10.
__device__ __forceinline__ Vec8 ld_keep256(const void* p) {
    unsigned long long a, b, c, d;
    asm("ld.global.nc.L2::evict_last.v4.b64 {%0,%1,%2,%3}, [%4];"
        : "=l"(a), "=l"(b), "=l"(c), "=l"(d) : "l"(p));
    Vec8 v;
    v.f[0] = __uint_as_float((unsigned)(a & 0xFFFFFFFFull));
    v.f[1] = __uint_as_float((unsigned)(a >> 32));
    v.f[2] = __uint_as_float((unsigned)(b & 0xFFFFFFFFull));
    v.f[3] = __uint_as_float((unsigned)(b >> 32));
    v.f[4] = __uint_as_float((unsigned)(c & 0xFFFFFFFFull));
    v.f[5] = __uint_as_float((unsigned)(c >> 32));
    v.f[6] = __uint_as_float((unsigned)(d & 0xFFFFFFFFull));
    v.f[7] = __uint_as_float((unsigned)(d >> 32));
    return v;
}

__global__ __launch_bounds__(128) void proto_fused_kernel(
    const float* __restrict__ qry,      // [N, DIM]
    const float* __restrict__ prompt,   // [N*N_WAY, DIM]
    const float* __restrict__ labels,   // [N, N_WAY] one-hot
    float* __restrict__ out)            // [2]: loss, acc
{
    __shared__ float s_loss[WARPS_PER_BLOCK];
    __shared__ int   s_corr[WARPS_PER_BLOCK];

    const int warp_in_blk = threadIdx.x >> 5;
    const int lane        = threadIdx.x & 31;
    const int query       = blockIdx.x * WARPS_PER_BLOCK + warp_in_blk;

    // One 32B chunk per lane per row: row = 256 floats = 32 lanes * 8 floats.
    const float* qrow = qry + (size_t)query * DIM + lane * 8;
    const float* prow = prompt + (size_t)query * N_WAY * DIM + lane * 8;

    Vec8 q = ld_keep256(qrow);

    float dist[N_WAY];
#pragma unroll
    for (int w = 0; w < N_WAY; ++w) {
        Vec8 p = ld_keep256(prow + w * DIM);
        float s = 0.0f;
#pragma unroll
        for (int i = 0; i < 8; ++i) {
            float dx = q.f[i] - p.f[i];
            s += dx * dx;
        }
        dist[w] = s;
    }

#pragma unroll
    for (int off = 16; off > 0; off >>= 1) {
#pragma unroll
        for (int w = 0; w < N_WAY; ++w)
            dist[w] += __shfl_xor_sync(0xFFFFFFFFu, dist[w], off);
    }

    if (lane == 0) {
        float mind = dist[0];
        int   amin = 0;
#pragma unroll
        for (int w = 1; w < N_WAY; ++w)
            if (dist[w] < mind) { mind = dist[w]; amin = w; }

        float sumexp = 0.0f;
#pragma unroll
        for (int w = 0; w < N_WAY; ++w)
            sumexp += __expf(mind - dist[w]);
        float lse = logf(sumexp);

        const float* lbl = labels + (size_t)query * N_WAY;
        int label = 0;
#pragma unroll
        for (int w = N_WAY - 1; w >= 1; --w)
            if (lbl[w] > 0.5f) label = w;

        float logp = (mind - dist[label]) - lse;   // log_softmax at label
        s_loss[warp_in_blk] = -logp;
        s_corr[warp_in_blk] = (amin == label) ? 1 : 0;
    }
    __syncthreads();

    if (threadIdx.x == 0) {
        float bl = 0.0f;
        int   bc = 0;
#pragma unroll
        for (int i = 0; i < WARPS_PER_BLOCK; ++i) { bl += s_loss[i]; bc += s_corr[i]; }
        atomicAdd(&g_loss_sum, (double)bl);
        atomicAdd(&g_correct, bc);

        __threadfence();
        unsigned int t = atomicAdd(&g_ticket, 1u);
        if (t == GRID_BLOCKS - 1) {
            // Last block: finalize and reset for the next graph replay.
            out[0] = (float)(g_loss_sum / (double)N_QUERIES);
            out[1] = (float)g_correct / (float)N_QUERIES;
            g_loss_sum = 0.0;
            g_correct  = 0;
            g_ticket   = 0;
        }
    }
}

extern "C" void kernel_launch(void* const* d_in, const int* in_sizes, int n_in,
                              void* d_out, int out_size) {
    const float* qry    = (const float*)d_in[0];
    const float* prompt = (const float*)d_in[1];
    const float* labels = (const float*)d_in[2];
    float* out = (float*)d_out;

    proto_fused_kernel<<<GRID_BLOCKS, 128>>>(qry, prompt, labels, out);
}

// round 14
// speedup vs baseline: 1.1232x; 1.1232x over previous
#include <cuda_runtime.h>
#include <cuda_bf16.h>
#include <math.h>

#define N_QUERIES 8192
#define N_WAY 5
#define DIM 256
#define WARPS_PER_BLOCK 8
#define GRID_BLOCKS (N_QUERIES / WARPS_PER_BLOCK)   // 1024

// Accumulators. Zero at module load; the last finishing block resets them
// after producing the output, so every graph replay starts from zero.
__device__ double       g_loss_sum = 0.0;
__device__ int          g_correct  = 0;
__device__ unsigned int g_ticket   = 0;

// FINAL (pinned floor config, reproduced at 11.3/11.5us):
//  - one warp per query, plain float4 loads, default caching
//  - compiler-chosen 32-reg schedule, 256-thread blocks, ~69% occupancy
//  - single fused launch; last-block-done finalize with self-reset
// Measured decomposition: ~7.7us memory at the ~6.3TB/s streaming cap
// + ~3.6us single-launch overhead. All alternative schedules/cache policies
// (MLP batching, __ldcs, evict_last, 256-bit loads, fmaf/ballot) measured
// neutral or worse.
__global__ __launch_bounds__(256) void proto_fused_kernel(
    const float* __restrict__ qry,      // [N, DIM]
    const float* __restrict__ prompt,   // [N*N_WAY, DIM]
    const float* __restrict__ labels,   // [N, N_WAY] one-hot
    float* __restrict__ out)            // [2]: loss, acc
{
    __shared__ float s_loss[WARPS_PER_BLOCK];
    __shared__ int   s_corr[WARPS_PER_BLOCK];

    const int warp_in_blk = threadIdx.x >> 5;
    const int lane        = threadIdx.x & 31;
    const int query       = blockIdx.x * WARPS_PER_BLOCK + warp_in_blk;

    // ---- per-query distance computation (one warp per query) ----
    const float4* q4 = reinterpret_cast<const float4*>(qry + (size_t)query * DIM);
    float4 qa = q4[lane];
    float4 qb = q4[lane + 32];

    float dist[N_WAY];
#pragma unroll
    for (int w = 0; w < N_WAY; ++w) {
        const float4* p4 = reinterpret_cast<const float4*>(
            prompt + ((size_t)query * N_WAY + w) * DIM);
        float4 pa = p4[lane];
        float4 pb = p4[lane + 32];
        float dx, s;
        dx = qa.x - pa.x; s  = dx * dx;
        dx = qa.y - pa.y; s += dx * dx;
        dx = qa.z - pa.z; s += dx * dx;
        dx = qa.w - pa.w; s += dx * dx;
        dx = qb.x - pb.x; s += dx * dx;
        dx = qb.y - pb.y; s += dx * dx;
        dx = qb.z - pb.z; s += dx * dx;
        dx = qb.w - pb.w; s += dx * dx;
        dist[w] = s;
    }

#pragma unroll
    for (int off = 16; off > 0; off >>= 1) {
#pragma unroll
        for (int w = 0; w < N_WAY; ++w)
            dist[w] += __shfl_xor_sync(0xFFFFFFFFu, dist[w], off);
    }

    if (lane == 0) {
        float mind = dist[0];
        int   amin = 0;
#pragma unroll
        for (int w = 1; w < N_WAY; ++w)
            if (dist[w] < mind) { mind = dist[w]; amin = w; }

        float sumexp = 0.0f;
#pragma unroll
        for (int w = 0; w < N_WAY; ++w)
            sumexp += __expf(mind - dist[w]);
        float lse = logf(sumexp);

        const float* lbl = labels + (size_t)query * N_WAY;
        int label = 0;
#pragma unroll
        for (int w = N_WAY - 1; w >= 1; --w)
            if (lbl[w] > 0.5f) label = w;

        float logp = (mind - dist[label]) - lse;   // log_softmax at label
        s_loss[warp_in_blk] = -logp;
        s_corr[warp_in_blk] = (amin == label) ? 1 : 0;
    }
    __syncthreads();

    // ---- block reduce + single atomic per block ----
    if (threadIdx.x == 0) {
        float bl = 0.0f;
        int   bc = 0;
#pragma unroll
        for (int i = 0; i < WARPS_PER_BLOCK; ++i) { bl += s_loss[i]; bc += s_corr[i]; }
        atomicAdd(&g_loss_sum, (double)bl);
        atomicAdd(&g_correct, bc);

        __threadfence();
        unsigned int t = atomicAdd(&g_ticket, 1u);
        if (t == GRID_BLOCKS - 1) {
            // Last block: finalize and reset for the next graph replay.
            out[0] = (float)(g_loss_sum / (double)N_QUERIES);
            out[1] = (float)g_correct / (float)N_QUERIES;
            g_loss_sum = 0.0;
            g_correct  = 0;
            g_ticket   = 0;
        }
    }
}

extern "C" void kernel_launch(void* const* d_in, const int* in_sizes, int n_in,
                              void* d_out, int out_size) {
    const float* qry    = (const float*)d_in[0];
    const float* prompt = (const float*)d_in[1];
    const float* labels = (const float*)d_in[2];
    float* out = (float*)d_out;

    proto_fused_kernel<<<GRID_BLOCKS, 256>>>(qry, prompt, labels, out);
}